// round 3
// baseline (speedup 1.0000x reference)
#include <cuda_runtime.h>

#define B_ 16
#define S_ 8192
#define H_ 512
#define P_ 32
#define M_ (B_*S_)            // 131072 rows
#define SSPLIT 8
#define SCHUNK (S_/SSPLIT)    // 1024

// Scratch (device globals; no allocation anywhere)
__device__ float g_sc[B_*P_*S_];            // 16 MB: scores, then exp(score - max)
__device__ float g_sum[B_*P_];              // softmax denominators
__device__ float g_part[SSPLIT*B_*P_*H_];   // 8 MB: partial contexts per s-split

// ---------------------------------------------------------------------------
// K1: scores[b,p,s] = sum_h probe[p,h] * x[b,s,h]
// GEMM M=131072, N=32, K=512. CTA tile 128x32, BK=32, 128 threads,
// thread tile 8 rows x 4 probes.
// ---------------------------------------------------------------------------
__global__ __launch_bounds__(128) void k_scores(const float* __restrict__ x,
                                                const float* __restrict__ probe) {
    __shared__ float As[32][129];   // [k][row], pad 129 -> conflict-free
    __shared__ float Ps[32][32];    // [k][p]
    const int t  = threadIdx.x;
    const int m0 = blockIdx.x * 128;
    const int rg = t >> 3;          // 0..15 (row group of 8)
    const int cg = t & 7;           // 0..7  (probe group of 4)

    float acc[8][4];
#pragma unroll
    for (int i = 0; i < 8; i++)
#pragma unroll
        for (int q = 0; q < 4; q++) acc[i][q] = 0.0f;

    for (int kc = 0; kc < H_; kc += 32) {
        // Stage A tile: 128 rows x 32 k (coalesced float4 loads, transposed store)
#pragma unroll
        for (int i = 0; i < 8; i++) {
            int f4  = i * 128 + t;          // 0..1023
            int row = f4 >> 3;              // 0..127
            int j   = f4 & 7;               // float4 index within row chunk
            float4 v = *reinterpret_cast<const float4*>(
                x + (size_t)(m0 + row) * H_ + kc + j * 4);
            As[j*4+0][row] = v.x; As[j*4+1][row] = v.y;
            As[j*4+2][row] = v.z; As[j*4+3][row] = v.w;
        }
        // Stage probe tile: 32 p x 32 k, transposed to [k][p]
#pragma unroll
        for (int i = 0; i < 2; i++) {
            int f4 = i * 128 + t;           // 0..255
            int p  = f4 >> 3;               // 0..31
            int j  = f4 & 7;
            float4 v = *reinterpret_cast<const float4*>(
                probe + (size_t)p * H_ + kc + j * 4);
            Ps[j*4+0][p] = v.x; Ps[j*4+1][p] = v.y;
            Ps[j*4+2][p] = v.z; Ps[j*4+3][p] = v.w;
        }
        __syncthreads();

#pragma unroll
        for (int k = 0; k < 32; k++) {
            float a[8];
#pragma unroll
            for (int i = 0; i < 8; i++) a[i] = As[k][rg*8 + i];
            float4 pv = *reinterpret_cast<const float4*>(&Ps[k][cg*4]);
            float pb[4] = {pv.x, pv.y, pv.z, pv.w};
#pragma unroll
            for (int i = 0; i < 8; i++)
#pragma unroll
                for (int q = 0; q < 4; q++)
                    acc[i][q] = fmaf(a[i], pb[q], acc[i][q]);
        }
        __syncthreads();
    }

    // Write scores to [B, P, S] layout
#pragma unroll
    for (int i = 0; i < 8; i++) {
        int m = m0 + rg*8 + i;
        int b = m >> 13;              // m / S
        int s = m & (S_ - 1);
#pragma unroll
        for (int q = 0; q < 4; q++) {
            int p = cg*4 + q;
            g_sc[((size_t)(b * P_ + p)) * S_ + s] = acc[i][q];
        }
    }
}

// ---------------------------------------------------------------------------
// K2: per (b,p): m = max_s score; write exp(score - m) in place; store sum.
// ---------------------------------------------------------------------------
__global__ __launch_bounds__(256) void k_softmax() {
    __shared__ float red[256];
    const int idx = blockIdx.x;               // b*P + p
    float* row = g_sc + (size_t)idx * S_;
    const int t = threadIdx.x;

    float m = -1e30f;
    for (int i = t; i < S_; i += 256) m = fmaxf(m, row[i]);
    red[t] = m; __syncthreads();
    for (int o = 128; o > 0; o >>= 1) {
        if (t < o) red[t] = fmaxf(red[t], red[t + o]);
        __syncthreads();
    }
    m = red[0];
    __syncthreads();

    float sum = 0.0f;
    for (int i = t; i < S_; i += 256) {
        float e = expf(row[i] - m);
        row[i] = e;
        sum += e;
    }
    red[t] = sum; __syncthreads();
    for (int o = 128; o > 0; o >>= 1) {
        if (t < o) red[t] += red[t + o];
        __syncthreads();
    }
    if (t == 0) g_sum[idx] = red[0];
}

// ---------------------------------------------------------------------------
// K3: partial ctx[b,p,h] = sum_{s in split} w[b,p,s] * x[b,s,h]
// CTA: (s-split, h-tile of 128, b). Tile 32p x 128h, K-loop 1024 s in BK=32.
// 256 threads, thread tile 4p x 4h.
// ---------------------------------------------------------------------------
__global__ __launch_bounds__(256) void k_ctx(const float* __restrict__ x) {
    __shared__ float Ws[32][32];    // [s][p]
    __shared__ float Xs[32][128];   // [s][h]
    const int t  = threadIdx.x;
    const int ss = blockIdx.x;      // 0..7
    const int ht = blockIdx.y;      // 0..3
    const int b  = blockIdx.z;      // 0..15
    const int h0 = ht * 128;
    const int pg = t >> 5;          // 0..7  (probe group of 4)
    const int hg = t & 31;          // 0..31 (h group of 4)

    float acc[4][4];
#pragma unroll
    for (int i = 0; i < 4; i++)
#pragma unroll
        for (int q = 0; q < 4; q++) acc[i][q] = 0.0f;

    for (int sc = 0; sc < SCHUNK; sc += 32) {
        const int s0 = ss * SCHUNK + sc;
        // Stage W: 32p x 32s from g_sc (exp weights), transposed to [s][p]
        {
            int p = t >> 3;         // 0..31
            int j = t & 7;
            float4 v = *reinterpret_cast<const float4*>(
                g_sc + ((size_t)(b * P_ + p)) * S_ + s0 + j * 4);
            Ws[j*4+0][p] = v.x; Ws[j*4+1][p] = v.y;
            Ws[j*4+2][p] = v.z; Ws[j*4+3][p] = v.w;
        }
        // Stage X: 32s x 128h (direct, coalesced float4)
#pragma unroll
        for (int i = 0; i < 4; i++) {
            int f4 = i * 256 + t;   // 0..1023
            int si = f4 >> 5;       // 0..31
            int j  = f4 & 31;
            *reinterpret_cast<float4*>(&Xs[si][j*4]) =
                *reinterpret_cast<const float4*>(
                    x + ((size_t)b * S_ + s0 + si) * H_ + h0 + j * 4);
        }
        __syncthreads();

#pragma unroll
        for (int si = 0; si < 32; si++) {
            float4 w  = *reinterpret_cast<const float4*>(&Ws[si][pg*4]);
            float4 xv = *reinterpret_cast<const float4*>(&Xs[si][hg*4]);
            float wb[4] = {w.x, w.y, w.z, w.w};
            float xb[4] = {xv.x, xv.y, xv.z, xv.w};
#pragma unroll
            for (int i = 0; i < 4; i++)
#pragma unroll
                for (int q = 0; q < 4; q++)
                    acc[i][q] = fmaf(wb[i], xb[q], acc[i][q]);
        }
        __syncthreads();
    }

    // Write partials: [ss][b][p][h]
#pragma unroll
    for (int i = 0; i < 4; i++) {
        int p = pg*4 + i;
        size_t base = (((size_t)ss * B_ + b) * P_ + p) * H_ + h0 + hg * 4;
        float4 v = make_float4(acc[i][0], acc[i][1], acc[i][2], acc[i][3]);
        *reinterpret_cast<float4*>(&g_part[base]) = v;
    }
}

// ---------------------------------------------------------------------------
// K4: out[b, p*H + h] = (sum_ss part[ss,b,p,h]) / sum[b,p]
// ---------------------------------------------------------------------------
__global__ __launch_bounds__(256) void k_final(float* __restrict__ out) {
    const int idx = blockIdx.x * 256 + threadIdx.x;   // 0..262143
    const int b  = idx >> 14;                         // / (P*H)
    const int ph = idx & 16383;                       // p*H + h
    const int p  = ph >> 9;

    float s = 0.0f;
#pragma unroll
    for (int ss = 0; ss < SSPLIT; ss++)
        s += g_part[(size_t)ss * (B_*P_*H_) + (size_t)b * (P_*H_) + ph];
    out[idx] = s / g_sum[b * P_ + p];
}

// ---------------------------------------------------------------------------
extern "C" void kernel_launch(void* const* d_in, const int* in_sizes, int n_in,
                              void* d_out, int out_size) {
    const float* x     = (const float*)d_in[0];   // [B, S, H]
    const float* probe = (const float*)d_in[1];   // [P, H]
    float* out = (float*)d_out;                   // [B, P*H]

    k_scores <<< M_ / 128, 128 >>>(x, probe);
    k_softmax<<< B_ * P_, 256 >>>();
    k_ctx    <<< dim3(SSPLIT, H_ / 128, B_), 256 >>>(x);
    k_final  <<< (B_ * P_ * H_) / 256, 256 >>>(out);
}

// round 7
// speedup vs baseline: 1.4037x; 1.4037x over previous
#include <cuda_runtime.h>
#include <cuda_bf16.h>
#include <mma.h>
#include <cstdint>

using namespace nvcuda;

#define B_ 16
#define S_ 8192
#define H_ 512
#define P_ 32
#define M_ (B_*S_)
#define SSPLIT 8
#define SCHUNK (S_/SSPLIT)    // 1024

// Scratch (device globals; no allocation anywhere)
__device__ float g_sc[B_*P_*S_];            // 16 MB: scores, then exp(score-max)
__device__ float g_sum[B_*P_];              // softmax denominators
__device__ float g_part[SSPLIT*B_*P_*H_];   // 8 MB: partial contexts

// ---------------------------------------------------------------------------
// split a float4 into packed bf16 hi (uint2 = 4 bf16) and lo residual (uint2)
// ---------------------------------------------------------------------------
__device__ __forceinline__ uint32_t packbf2(__nv_bfloat16 a, __nv_bfloat16 b) {
    return (uint32_t)__bfloat16_as_ushort(a) |
           ((uint32_t)__bfloat16_as_ushort(b) << 16);
}
__device__ __forceinline__ void split4(float4 v, uint2& hi, uint2& lo) {
    __nv_bfloat16 h0 = __float2bfloat16_rn(v.x);
    __nv_bfloat16 h1 = __float2bfloat16_rn(v.y);
    __nv_bfloat16 h2 = __float2bfloat16_rn(v.z);
    __nv_bfloat16 h3 = __float2bfloat16_rn(v.w);
    __nv_bfloat16 l0 = __float2bfloat16_rn(v.x - __bfloat162float(h0));
    __nv_bfloat16 l1 = __float2bfloat16_rn(v.y - __bfloat162float(h1));
    __nv_bfloat16 l2 = __float2bfloat16_rn(v.z - __bfloat162float(h2));
    __nv_bfloat16 l3 = __float2bfloat16_rn(v.w - __bfloat162float(h3));
    hi = make_uint2(packbf2(h0, h1), packbf2(h2, h3));
    lo = make_uint2(packbf2(l0, l1), packbf2(l2, l3));
}

typedef wmma::fragment<wmma::matrix_a, 16, 16, 16, __nv_bfloat16, wmma::row_major> FragA;
typedef wmma::fragment<wmma::matrix_b, 16, 16, 16, __nv_bfloat16, wmma::col_major> FragBc;
typedef wmma::fragment<wmma::matrix_b, 16, 16, 16, __nv_bfloat16, wmma::row_major> FragBr;
typedef wmma::fragment<wmma::accumulator, 16, 16, 16, float> FragC;

// ===========================================================================
// K1: scores[b,p,s] = sum_h probe[p,h] * x[b,s,h]    (M=131072, N=32, K=512)
// CTA: 128 m-rows x 32 p, 256 threads (8 warps), K-chunks of 64.
// Warp w computes rows [w*16, w*16+16) x all 32 p (2 acc frags).
// A = x rows (row-major, ld 72), B = probe [p][k] (matrix_b col_major, ld 72).
// 3-term split-bf16: hi*hi + hi*lo + lo*hi.
// ===========================================================================
#define LD1 72
__global__ __launch_bounds__(256) void k_scores_w(const float* __restrict__ x,
                                                  const float* __restrict__ probe) {
    __shared__ alignas(128) unsigned char sm[46080];
    __nv_bfloat16* Ahi = reinterpret_cast<__nv_bfloat16*>(sm);           // [128][72]
    __nv_bfloat16* Alo = reinterpret_cast<__nv_bfloat16*>(sm + 18432);   // [128][72]
    __nv_bfloat16* Bhi = reinterpret_cast<__nv_bfloat16*>(sm + 36864);   // [32][72]
    __nv_bfloat16* Blo = reinterpret_cast<__nv_bfloat16*>(sm + 41472);   // [32][72]
    float* stage = reinterpret_cast<float*>(sm);                         // [32][132] overlay

    const int t = threadIdx.x, wid = t >> 5;
    const int m0 = blockIdx.x * 128;

    FragC acc[2];
    wmma::fill_fragment(acc[0], 0.0f);
    wmma::fill_fragment(acc[1], 0.0f);

    for (int kc = 0; kc < H_; kc += 64) {
        // stage A: 128 rows x 64 k  (2048 float4, 8 per thread)
#pragma unroll
        for (int i = 0; i < 8; i++) {
            int idx = i * 256 + t;
            int row = idx >> 4, j = idx & 15;
            float4 v = *reinterpret_cast<const float4*>(
                x + (size_t)(m0 + row) * H_ + kc + j * 4);
            uint2 hi, lo; split4(v, hi, lo);
            *reinterpret_cast<uint2*>(reinterpret_cast<char*>(Ahi) + row * 144 + j * 8) = hi;
            *reinterpret_cast<uint2*>(reinterpret_cast<char*>(Alo) + row * 144 + j * 8) = lo;
        }
        // stage B: 32 p x 64 k  (512 float4, 2 per thread)
#pragma unroll
        for (int i = 0; i < 2; i++) {
            int idx = i * 256 + t;
            int p = idx >> 4, j = idx & 15;
            float4 v = *reinterpret_cast<const float4*>(
                probe + (size_t)p * H_ + kc + j * 4);
            uint2 hi, lo; split4(v, hi, lo);
            *reinterpret_cast<uint2*>(reinterpret_cast<char*>(Bhi) + p * 144 + j * 8) = hi;
            *reinterpret_cast<uint2*>(reinterpret_cast<char*>(Blo) + p * 144 + j * 8) = lo;
        }
        __syncthreads();

#pragma unroll
        for (int kf = 0; kf < 4; kf++) {
            FragA ah, al;
            wmma::load_matrix_sync(ah, Ahi + wid * 16 * LD1 + kf * 16, LD1);
            wmma::load_matrix_sync(al, Alo + wid * 16 * LD1 + kf * 16, LD1);
#pragma unroll
            for (int c = 0; c < 2; c++) {
                FragBc bh, bl;
                wmma::load_matrix_sync(bh, Bhi + c * 16 * LD1 + kf * 16, LD1);
                wmma::load_matrix_sync(bl, Blo + c * 16 * LD1 + kf * 16, LD1);
                wmma::mma_sync(acc[c], ah, bh, acc[c]);
                wmma::mma_sync(acc[c], ah, bl, acc[c]);
                wmma::mma_sync(acc[c], al, bh, acc[c]);
            }
        }
        __syncthreads();
    }

    // store acc col-major into stage[p][132]: element (m-row r, p) -> stage[p*132 + r]
#pragma unroll
    for (int c = 0; c < 2; c++)
        wmma::store_matrix_sync(stage + (size_t)c * 16 * 132 + wid * 16, acc[c],
                                132, wmma::mem_col_major);
    __syncthreads();

    // write out: per p, 128 contiguous s
    const int b = m0 >> 13;
    const int s0 = m0 & (S_ - 1);
    const int p = t >> 3, j = t & 7;
#pragma unroll
    for (int i = 0; i < 4; i++) {
        int r0 = i * 32 + j * 4;
        float4 v = *reinterpret_cast<const float4*>(&stage[p * 132 + r0]);
        *reinterpret_cast<float4*>(
            &g_sc[((size_t)(b * P_ + p)) * S_ + s0 + r0]) = v;
    }
}

// ===========================================================================
// K2: softmax per (b,p): exp(x - max) in place, store sum.
// ===========================================================================
__global__ __launch_bounds__(256) void k_softmax() {
    __shared__ float red[256];
    const int idx = blockIdx.x;
    float* row = g_sc + (size_t)idx * S_;
    const int t = threadIdx.x;

    float m = -1e30f;
    for (int i = t; i < S_; i += 256) m = fmaxf(m, row[i]);
    red[t] = m; __syncthreads();
    for (int o = 128; o > 0; o >>= 1) {
        if (t < o) red[t] = fmaxf(red[t], red[t + o]);
        __syncthreads();
    }
    m = red[0];
    __syncthreads();

    float sum = 0.0f;
    for (int i = t; i < S_; i += 256) {
        float e = expf(row[i] - m);
        row[i] = e;
        sum += e;
    }
    red[t] = sum; __syncthreads();
    for (int o = 128; o > 0; o >>= 1) {
        if (t < o) red[t] += red[t + o];
        __syncthreads();
    }
    if (t == 0) g_sum[idx] = red[0];
}

// ===========================================================================
// K3: partial ctx[b,p,h] = sum_{s in split} w[b,p,s] * x[b,s,h]
// CTA = (ss, h-tile of 64, b), 256 threads (8 warps).  M=32 p, N=64 h, K=1024 s.
// A = w[p][s] row-major (natural from g_sc), B = x[s][h] row-major — no transpose.
// Warp w: p-slab pr=w>>2 (16 p), h-slab hc=w&3 (16 h), one acc frag.
// ===========================================================================
#define LD2 72
__global__ __launch_bounds__(256) void k_ctx_w(const float* __restrict__ x) {
    __shared__ alignas(128) unsigned char sm[27648];
    __nv_bfloat16* Whi = reinterpret_cast<__nv_bfloat16*>(sm);           // [32][72]
    __nv_bfloat16* Wlo = reinterpret_cast<__nv_bfloat16*>(sm + 4608);    // [32][72]
    __nv_bfloat16* Xhi = reinterpret_cast<__nv_bfloat16*>(sm + 9216);    // [64][72]
    __nv_bfloat16* Xlo = reinterpret_cast<__nv_bfloat16*>(sm + 18432);   // [64][72]
    float* stage = reinterpret_cast<float*>(sm);                         // [32][68] overlay

    const int t = threadIdx.x, wid = t >> 5;
    const int ss = blockIdx.x;            // 0..7
    const int h0 = blockIdx.y * 64;       // 0..7 tiles
    const int b  = blockIdx.z;
    const int pr = wid >> 2, hc = wid & 3;

    FragC acc;
    wmma::fill_fragment(acc, 0.0f);

    const size_t xbase = (size_t)b * S_ + (size_t)ss * SCHUNK;
    const size_t wbase = (size_t)b * P_ * S_ + (size_t)ss * SCHUNK;

    for (int c = 0; c < SCHUNK / 64; c++) {
        const int s0 = c * 64;
        // stage W: 32 p x 64 s (512 float4, 2 per thread)
#pragma unroll
        for (int i = 0; i < 2; i++) {
            int idx = i * 256 + t;
            int p = idx >> 4, j = idx & 15;
            float4 v = *reinterpret_cast<const float4*>(
                g_sc + wbase + (size_t)p * S_ + s0 + j * 4);
            uint2 hi, lo; split4(v, hi, lo);
            *reinterpret_cast<uint2*>(reinterpret_cast<char*>(Whi) + p * 144 + j * 8) = hi;
            *reinterpret_cast<uint2*>(reinterpret_cast<char*>(Wlo) + p * 144 + j * 8) = lo;
        }
        // stage X: 64 s x 64 h (1024 float4, 4 per thread)
#pragma unroll
        for (int i = 0; i < 4; i++) {
            int idx = i * 256 + t;
            int s = idx >> 4, j = idx & 15;
            float4 v = *reinterpret_cast<const float4*>(
                x + (xbase + s0 + s) * H_ + h0 + j * 4);
            uint2 hi, lo; split4(v, hi, lo);
            *reinterpret_cast<uint2*>(reinterpret_cast<char*>(Xhi) + s * 144 + j * 8) = hi;
            *reinterpret_cast<uint2*>(reinterpret_cast<char*>(Xlo) + s * 144 + j * 8) = lo;
        }
        __syncthreads();

#pragma unroll
        for (int kf = 0; kf < 4; kf++) {
            FragA ah, al;
            wmma::load_matrix_sync(ah, Whi + pr * 16 * LD2 + kf * 16, LD2);
            wmma::load_matrix_sync(al, Wlo + pr * 16 * LD2 + kf * 16, LD2);
            FragBr bh, bl;
            wmma::load_matrix_sync(bh, Xhi + kf * 16 * LD2 + hc * 16, LD2);
            wmma::load_matrix_sync(bl, Xlo + kf * 16 * LD2 + hc * 16, LD2);
            wmma::mma_sync(acc, ah, bh, acc);
            wmma::mma_sync(acc, ah, bl, acc);
            wmma::mma_sync(acc, al, bh, acc);
        }
        __syncthreads();
    }

    // store acc row-major into stage[32][68]
    wmma::store_matrix_sync(stage + (size_t)pr * 16 * 68 + hc * 16, acc,
                            68, wmma::mem_row_major);
    __syncthreads();

    // write out 32 p x 64 h (512 float4, 2 per thread)
#pragma unroll
    for (int i = 0; i < 2; i++) {
        int idx = i * 256 + t;
        int p = idx >> 4, j = idx & 15;
        float4 v = *reinterpret_cast<const float4*>(&stage[p * 68 + j * 4]);
        *reinterpret_cast<float4*>(
            &g_part[(((size_t)ss * B_ + b) * P_ + p) * H_ + h0 + j * 4]) = v;
    }
}

// ===========================================================================
// K4: reduce s-split partials + normalize
// ===========================================================================
__global__ __launch_bounds__(256) void k_final(float* __restrict__ out) {
    const int idx = blockIdx.x * 256 + threadIdx.x;
    const int b  = idx >> 14;
    const int ph = idx & 16383;
    const int p  = ph >> 9;

    float s = 0.0f;
#pragma unroll
    for (int ss = 0; ss < SSPLIT; ss++)
        s += g_part[(size_t)ss * (B_*P_*H_) + (size_t)b * (P_*H_) + ph];
    out[idx] = s / g_sum[b * P_ + p];
}

// ---------------------------------------------------------------------------
extern "C" void kernel_launch(void* const* d_in, const int* in_sizes, int n_in,
                              void* d_out, int out_size) {
    const float* x     = (const float*)d_in[0];   // [B, S, H]
    const float* probe = (const float*)d_in[1];   // [P, H]
    float* out = (float*)d_out;                   // [B, P*H]

    k_scores_w<<< M_ / 128, 256 >>>(x, probe);
    k_softmax <<< B_ * P_, 256 >>>();
    k_ctx_w   <<< dim3(SSPLIT, H_ / 64, B_), 256 >>>(x);
    k_final   <<< (B_ * P_ * H_) / 256, 256 >>>(out);
}

// round 12
// speedup vs baseline: 1.4368x; 1.0235x over previous
#include <cuda_runtime.h>
#include <cuda_bf16.h>
#include <mma.h>
#include <cstdint>

using namespace nvcuda;

#define B_ 16
#define S_ 8192
#define H_ 512
#define P_ 32
#define NSPL 9            // s-splits -> 9*16 = 144 CTAs = 1 wave

// Scratch (device globals; no allocation anywhere)
__device__ float g_part[NSPL*B_*P_*H_];   // per-split unnormalized ctx
__device__ float g_m[NSPL*B_*P_];         // per-split running max
__device__ float g_l[NSPL*B_*P_];         // per-split exp-sum

// ---------------- smem layout (bytes) ----------------
#define LDX 520                               // elements per row (512 + 8 pad)
#define LDS_ 36                               // S tile stride (floats, 144B = 16B mult)
#define OFF_PHI   0
#define OFF_PLO   (OFF_PHI + 32*LDX*2)        // 33280
#define OFF_X     (OFF_PLO + 32*LDX*2)        // 66560
#define XBUF_SZ   (32*LDX*2*2)                // hi+lo per buffer = 66560
#define OFF_S0    (OFF_X + 2*XBUF_SZ)         // 199680
#define OFF_S1    (OFF_S0 + 32*LDS_*4)        // 204288
#define OFF_EHI   (OFF_S1 + 32*LDS_*4)        // 208896
#define OFF_ELO   (OFF_EHI + 32*48*2)         // 211968
#define OFF_M     (OFF_ELO + 32*48*2)         // 215040
#define OFF_L     (OFF_M + 32*4)              // 215168
#define OFF_SC    (OFF_L + 32*4)              // 215296
#define SMEM_TOT  (OFF_SC + 32*4)             // 215424

__device__ __forceinline__ uint32_t packbf2(__nv_bfloat16 a, __nv_bfloat16 b) {
    return (uint32_t)__bfloat16_as_ushort(a) |
           ((uint32_t)__bfloat16_as_ushort(b) << 16);
}
__device__ __forceinline__ void split4(float4 v, uint2& hi, uint2& lo) {
    __nv_bfloat16 h0 = __float2bfloat16_rn(v.x);
    __nv_bfloat16 h1 = __float2bfloat16_rn(v.y);
    __nv_bfloat16 h2 = __float2bfloat16_rn(v.z);
    __nv_bfloat16 h3 = __float2bfloat16_rn(v.w);
    __nv_bfloat16 l0 = __float2bfloat16_rn(v.x - __bfloat162float(h0));
    __nv_bfloat16 l1 = __float2bfloat16_rn(v.y - __bfloat162float(h1));
    __nv_bfloat16 l2 = __float2bfloat16_rn(v.z - __bfloat162float(h2));
    __nv_bfloat16 l3 = __float2bfloat16_rn(v.w - __bfloat162float(h3));
    hi = make_uint2(packbf2(h0, h1), packbf2(h2, h3));
    lo = make_uint2(packbf2(l0, l1), packbf2(l2, l3));
}

typedef wmma::fragment<wmma::matrix_a, 16, 16, 16, __nv_bfloat16, wmma::row_major> FA;
typedef wmma::fragment<wmma::matrix_b, 16, 16, 16, __nv_bfloat16, wmma::col_major> FBc;
typedef wmma::fragment<wmma::matrix_b, 16, 16, 16, __nv_bfloat16, wmma::row_major> FBr;
typedef wmma::fragment<wmma::accumulator, 16, 16, 16, float> FC;

// ===========================================================================
// Fused kernel. CTA = (s-split ss, batch b). 256 threads (8 warps).
// Chunk = 32 s. Per chunk: GEMM1 scores (32s x 32p, K=512, split-bf16 3-term),
// online softmax stats + E tile, acc rescale, GEMM2 ctx += E^T * x (K=32).
// x is read from HBM exactly once.
// ===========================================================================
__global__ __launch_bounds__(256, 1) void k_fused(const float* __restrict__ x,
                                                  const float* __restrict__ probe) {
    extern __shared__ unsigned char sm[];
    __nv_bfloat16* Phi = reinterpret_cast<__nv_bfloat16*>(sm + OFF_PHI);
    __nv_bfloat16* Plo = reinterpret_cast<__nv_bfloat16*>(sm + OFF_PLO);
    float* S0  = reinterpret_cast<float*>(sm + OFF_S0);
    float* S1  = reinterpret_cast<float*>(sm + OFF_S1);
    __nv_bfloat16* Ehi = reinterpret_cast<__nv_bfloat16*>(sm + OFF_EHI);
    __nv_bfloat16* Elo = reinterpret_cast<__nv_bfloat16*>(sm + OFF_ELO);
    float* smM  = reinterpret_cast<float*>(sm + OFF_M);
    float* smL  = reinterpret_cast<float*>(sm + OFF_L);
    float* smSC = reinterpret_cast<float*>(sm + OFF_SC);

    const int t = threadIdx.x, wid = t >> 5, lane = t & 31;
    const int ss = blockIdx.x, b = blockIdx.y;
    const int nsub = (ss < 4) ? 29 : 28;               // 4*29 + 5*28 = 256
    const int sub0 = ss * 28 + (ss < 4 ? ss : 4);
    const size_t xb = (size_t)b * S_ * H_;

    // ---- load probes (once): 32 x 512, split hi/lo
#pragma unroll
    for (int i = 0; i < 16; i++) {
        int idx = i * 256 + t;
        int p = idx >> 7, j = idx & 127;
        float4 v = *reinterpret_cast<const float4*>(probe + (size_t)p * H_ + j * 4);
        uint2 hi, lo; split4(v, hi, lo);
        *reinterpret_cast<uint2*>(reinterpret_cast<char*>(Phi) + p * 1040 + j * 8) = hi;
        *reinterpret_cast<uint2*>(reinterpret_cast<char*>(Plo) + p * 1040 + j * 8) = lo;
    }
    // ---- load chunk 0 into buffer 0
    {
        __nv_bfloat16* Xh = reinterpret_cast<__nv_bfloat16*>(sm + OFF_X);
        __nv_bfloat16* Xl = Xh + 32 * LDX;
#pragma unroll
        for (int i = 0; i < 16; i++) {
            int idx = i * 256 + t;
            int row = idx >> 7, j = idx & 127;
            float4 v = *reinterpret_cast<const float4*>(
                x + xb + ((size_t)sub0 * 32 + row) * H_ + j * 4);
            uint2 hi, lo; split4(v, hi, lo);
            *reinterpret_cast<uint2*>(reinterpret_cast<char*>(Xh) + row * 1040 + j * 8) = hi;
            *reinterpret_cast<uint2*>(reinterpret_cast<char*>(Xl) + row * 1040 + j * 8) = lo;
        }
    }
    if (t < 32) { smM[t] = -1e30f; smL[t] = 0.0f; }
    __syncthreads();

    FC acc[2][4];
#pragma unroll
    for (int pt = 0; pt < 2; pt++)
#pragma unroll
        for (int ht = 0; ht < 4; ht++) wmma::fill_fragment(acc[pt][ht], 0.0f);

    const int ms = wid & 1, np = (wid >> 1) & 1, kh = (wid >> 2) & 1;

    for (int c = 0; c < nsub; c++) {
        const int cur = c & 1;
        __nv_bfloat16* Xh = reinterpret_cast<__nv_bfloat16*>(sm + OFF_X + cur * XBUF_SZ);
        __nv_bfloat16* Xl = Xh + 32 * LDX;

        // ---- GEMM1: S[32s, 32p], each warp one 16x16 quadrant x half-K
        {
            FC sacc;
            wmma::fill_fragment(sacc, 0.0f);
#pragma unroll
            for (int kk = 0; kk < 16; kk++) {
                const int ko = kh * 256 + kk * 16;
                FA ah, al;
                wmma::load_matrix_sync(ah, Xh + ms * 16 * LDX + ko, LDX);
                wmma::load_matrix_sync(al, Xl + ms * 16 * LDX + ko, LDX);
                FBc bh, bl;
                wmma::load_matrix_sync(bh, Phi + np * 16 * LDX + ko, LDX);
                wmma::load_matrix_sync(bl, Plo + np * 16 * LDX + ko, LDX);
                wmma::mma_sync(sacc, ah, bh, sacc);
                wmma::mma_sync(sacc, ah, bl, sacc);
                wmma::mma_sync(sacc, al, bh, sacc);
            }
            float* Sd = kh ? S1 : S0;
            wmma::store_matrix_sync(Sd + ms * 16 * LDS_ + np * 16, sacc, LDS_,
                                    wmma::mem_row_major);
        }

        // ---- prefetch next chunk into the other buffer
        if (c + 1 < nsub) {
            __nv_bfloat16* Nh = reinterpret_cast<__nv_bfloat16*>(
                sm + OFF_X + (cur ^ 1) * XBUF_SZ);
            __nv_bfloat16* Nl = Nh + 32 * LDX;
#pragma unroll
            for (int i = 0; i < 16; i++) {
                int idx = i * 256 + t;
                int row = idx >> 7, j = idx & 127;
                float4 v = *reinterpret_cast<const float4*>(
                    x + xb + ((size_t)(sub0 + c + 1) * 32 + row) * H_ + j * 4);
                uint2 hi, lo; split4(v, hi, lo);
                *reinterpret_cast<uint2*>(reinterpret_cast<char*>(Nh) + row * 1040 + j * 8) = hi;
                *reinterpret_cast<uint2*>(reinterpret_cast<char*>(Nl) + row * 1040 + j * 8) = lo;
            }
        }
        __syncthreads();   // S complete

        // ---- online-softmax stats + E tile (warp w handles probes 4w..4w+3)
#pragma unroll
        for (int c4 = 0; c4 < 4; c4++) {
            const int p = wid * 4 + c4;
            float v = S0[lane * LDS_ + p] + S1[lane * LDS_ + p];
            float cm = v;
#pragma unroll
            for (int o = 16; o > 0; o >>= 1)
                cm = fmaxf(cm, __shfl_xor_sync(0xFFFFFFFFu, cm, o));
            const float mo = smM[p];
            const float mn = fmaxf(mo, cm);
            const float e = __expf(v - mn);
            float se = e;
#pragma unroll
            for (int o = 16; o > 0; o >>= 1)
                se += __shfl_xor_sync(0xFFFFFFFFu, se, o);
            if (lane == 0) {
                const float sc = __expf(mo - mn);
                smSC[p] = sc;
                smM[p]  = mn;
                smL[p]  = smL[p] * sc + se;
            }
            __nv_bfloat16 eh = __float2bfloat16_rn(e);
            __nv_bfloat16 el = __float2bfloat16_rn(e - __bfloat162float(eh));
            Ehi[p * 48 + lane] = eh;
            Elo[p * 48 + lane] = el;
        }
        __syncthreads();   // E + scale visible

        // ---- rescale accumulator (m16n8k16 pair layout: x[0..1] row lane>>2,
        //      x[2..3] row+8; x[4..7] second 8-col group, same rows)
#pragma unroll
        for (int pt = 0; pt < 2; pt++) {
            const float sa = smSC[pt * 16 + (lane >> 2)];
            const float sb = smSC[pt * 16 + (lane >> 2) + 8];
#pragma unroll
            for (int ht = 0; ht < 4; ht++)
#pragma unroll
                for (int i = 0; i < 8; i++)
                    acc[pt][ht].x[i] *= (i & 2) ? sb : sa;
        }

        // ---- GEMM2: ctx[32p, 64h-slab] += E[32p,32s] * X[32s, 64h]
#pragma unroll
        for (int kk = 0; kk < 2; kk++) {
            FA ah[2], al[2];
#pragma unroll
            for (int pt = 0; pt < 2; pt++) {
                wmma::load_matrix_sync(ah[pt], Ehi + pt * 16 * 48 + kk * 16, 48);
                wmma::load_matrix_sync(al[pt], Elo + pt * 16 * 48 + kk * 16, 48);
            }
#pragma unroll
            for (int ht = 0; ht < 4; ht++) {
                FBr bh, bl;
                wmma::load_matrix_sync(bh, Xh + kk * 16 * LDX + wid * 64 + ht * 16, LDX);
                wmma::load_matrix_sync(bl, Xl + kk * 16 * LDX + wid * 64 + ht * 16, LDX);
#pragma unroll
                for (int pt = 0; pt < 2; pt++) {
                    wmma::mma_sync(acc[pt][ht], ah[pt], bh, acc[pt][ht]);
                    wmma::mma_sync(acc[pt][ht], ah[pt], bl, acc[pt][ht]);
                    wmma::mma_sync(acc[pt][ht], al[pt], bh, acc[pt][ht]);
                }
            }
        }
        __syncthreads();   // cur buffer free for next prefetch target
    }

    // ---- epilogue: write unnormalized ctx + (m, l)
#pragma unroll
    for (int pt = 0; pt < 2; pt++)
#pragma unroll
        for (int ht = 0; ht < 4; ht++)
            wmma::store_matrix_sync(
                g_part + (((size_t)(ss * B_ + b)) * P_ + pt * 16) * H_ + wid * 64 + ht * 16,
                acc[pt][ht], H_, wmma::mem_row_major);
    if (wid == 0) {
        g_m[(ss * B_ + b) * P_ + lane] = smM[lane];
        g_l[(ss * B_ + b) * P_ + lane] = smL[lane];
    }
}

// ===========================================================================
// Combine: out[b, p*H+h] = sum_ss part*w_ss / sum_ss l*w_ss, w_ss=exp(m_ss-m_g)
// ===========================================================================
__global__ __launch_bounds__(256) void k_final(float* __restrict__ out) {
    const int idx = blockIdx.x * 256 + threadIdx.x;     // 0..262143
    const int b  = idx >> 14;
    const int ph = idx & 16383;
    const int p  = ph >> 9;
    const int h  = ph & 511;

    float mg = -1e30f;
#pragma unroll
    for (int ss = 0; ss < NSPL; ss++)
        mg = fmaxf(mg, g_m[(ss * B_ + b) * P_ + p]);
    float num = 0.0f, den = 0.0f;
#pragma unroll
    for (int ss = 0; ss < NSPL; ss++) {
        const int base = (ss * B_ + b) * P_ + p;
        const float w = __expf(g_m[base] - mg);
        num += g_part[(size_t)base * H_ + h] * w;
        den += g_l[base] * w;
    }
    out[idx] = num / den;
}

// ---------------------------------------------------------------------------
extern "C" void kernel_launch(void* const* d_in, const int* in_sizes, int n_in,
                              void* d_out, int out_size) {
    const float* x     = (const float*)d_in[0];   // [B, S, H]
    const float* probe = (const float*)d_in[1];   // [P, H]
    float* out = (float*)d_out;                   // [B, P*H]

    cudaFuncSetAttribute(k_fused, cudaFuncAttributeMaxDynamicSharedMemorySize,
                         SMEM_TOT);

    k_fused<<< dim3(NSPL, B_), 256, SMEM_TOT >>>(x, probe);
    k_final<<< (B_ * P_ * H_) / 256, 256 >>>(out);
}

// round 13
// speedup vs baseline: 1.6299x; 1.1344x over previous
#include <cuda_runtime.h>
#include <cuda_bf16.h>
#include <mma.h>
#include <cstdint>

using namespace nvcuda;

#define B_ 16
#define S_ 8192
#define H_ 512
#define P_ 32
#define NSPL 9            // s-splits -> 9*16 = 144 CTAs = 1 wave

// Scratch (device globals; no allocation anywhere)
__device__ float g_part[NSPL*B_*P_*H_];   // per-split unnormalized ctx
__device__ float g_m[NSPL*B_*P_];         // per-split running max
__device__ float g_l[NSPL*B_*P_];         // per-split exp-sum

// ---------------- smem layout (bytes) ----------------
#define LDX 520                               // elements per row (512 + 8 pad)
#define LDS_ 36                               // S tile stride (floats, 144B)
#define LDE 48                                // E tile stride (bf16)
#define OFF_PHI   0
#define OFF_PLO   (OFF_PHI + 32*LDX*2)        // 33280
#define OFF_X     (OFF_PLO + 32*LDX*2)        // 66560
#define XBUF_SZ   (32*LDX*2*2)                // hi+lo per buffer = 66560
#define OFF_S     (OFF_X + 2*XBUF_SZ)         // 199680, 4 bufs x 32*36*4
#define SBUF_SZ   (32*LDS_*4)                 // 4608
#define OFF_EHI   (OFF_S + 4*SBUF_SZ)         // 218112
#define OFF_ELO   (OFF_EHI + 32*LDE*2)        // 221184
#define OFF_M     (OFF_ELO + 32*LDE*2)        // 224256
#define OFF_L     (OFF_M + 128)               // 224384
#define OFF_SC    (OFF_L + 128)               // 224512
#define SMEM_TOT  (OFF_SC + 128)              // 224640

// fast fp32 -> (hi, lo) bf16 split for a float4: 2 elems per cvt instruction
__device__ __forceinline__ void split4(float4 v, uint2& hi, uint2& lo) {
    uint32_t h01, h23;
    asm("cvt.rn.bf16x2.f32 %0, %1, %2;" : "=r"(h01) : "f"(v.y), "f"(v.x));
    asm("cvt.rn.bf16x2.f32 %0, %1, %2;" : "=r"(h23) : "f"(v.w), "f"(v.z));
    float hx = __uint_as_float(h01 << 16);
    float hy = __uint_as_float(h01 & 0xFFFF0000u);
    float hz = __uint_as_float(h23 << 16);
    float hw = __uint_as_float(h23 & 0xFFFF0000u);
    uint32_t l01, l23;
    asm("cvt.rn.bf16x2.f32 %0, %1, %2;" : "=r"(l01) : "f"(v.y - hy), "f"(v.x - hx));
    asm("cvt.rn.bf16x2.f32 %0, %1, %2;" : "=r"(l23) : "f"(v.w - hw), "f"(v.z - hz));
    hi = make_uint2(h01, h23);
    lo = make_uint2(l01, l23);
}

typedef wmma::fragment<wmma::matrix_a, 16, 16, 16, __nv_bfloat16, wmma::row_major> FA;
typedef wmma::fragment<wmma::matrix_b, 16, 16, 16, __nv_bfloat16, wmma::col_major> FBc;
typedef wmma::fragment<wmma::matrix_b, 16, 16, 16, __nv_bfloat16, wmma::row_major> FBr;
typedef wmma::fragment<wmma::accumulator, 16, 16, 16, float> FC;

// ===========================================================================
// Fused flash-style kernel. CTA = (s-split ss, batch b). 512 threads / 16 warps.
// Chunk = 32 s: GEMM1 S=x*P^T (K=512 split over 4 warp-quarters), online
// softmax, acc rescale, GEMM2 ctx += E*x. x read from HBM exactly once.
// ===========================================================================
__global__ __launch_bounds__(512, 1) void k_fused(const float* __restrict__ x,
                                                  const float* __restrict__ probe) {
    extern __shared__ unsigned char sm[];
    __nv_bfloat16* Phi = reinterpret_cast<__nv_bfloat16*>(sm + OFF_PHI);
    __nv_bfloat16* Plo = reinterpret_cast<__nv_bfloat16*>(sm + OFF_PLO);
    float* Sb  = reinterpret_cast<float*>(sm + OFF_S);        // 4 x [32][36]
    __nv_bfloat16* Ehi = reinterpret_cast<__nv_bfloat16*>(sm + OFF_EHI);
    __nv_bfloat16* Elo = reinterpret_cast<__nv_bfloat16*>(sm + OFF_ELO);
    float* smM  = reinterpret_cast<float*>(sm + OFF_M);
    float* smL  = reinterpret_cast<float*>(sm + OFF_L);
    float* smSC = reinterpret_cast<float*>(sm + OFF_SC);

    const int t = threadIdx.x, wid = t >> 5, lane = t & 31;
    const int ss = blockIdx.x, b = blockIdx.y;
    const int nsub = (ss < 4) ? 29 : 28;               // 4*29 + 5*28 = 256
    const int sub0 = ss * 28 + (ss < 4 ? ss : 4);
    const size_t xb = (size_t)b * S_ * H_;

    // ---- load probes (once): 32 x 512 -> hi/lo (8 float4 per thread)
#pragma unroll
    for (int i = 0; i < 8; i++) {
        int idx = i * 512 + t;
        int p = idx >> 7, j = idx & 127;
        float4 v = *reinterpret_cast<const float4*>(probe + (size_t)p * H_ + j * 4);
        uint2 hi, lo; split4(v, hi, lo);
        *reinterpret_cast<uint2*>(reinterpret_cast<char*>(Phi) + p * 1040 + j * 8) = hi;
        *reinterpret_cast<uint2*>(reinterpret_cast<char*>(Plo) + p * 1040 + j * 8) = lo;
    }
    // ---- chunk 0 into buffer 0
    {
        __nv_bfloat16* Xh = reinterpret_cast<__nv_bfloat16*>(sm + OFF_X);
#pragma unroll
        for (int i = 0; i < 8; i++) {
            int idx = i * 512 + t;
            int row = idx >> 7, j = idx & 127;
            float4 v = *reinterpret_cast<const float4*>(
                x + xb + ((size_t)sub0 * 32 + row) * H_ + j * 4);
            uint2 hi, lo; split4(v, hi, lo);
            *reinterpret_cast<uint2*>(reinterpret_cast<char*>(Xh) + row * 1040 + j * 8) = hi;
            *reinterpret_cast<uint2*>(reinterpret_cast<char*>(Xh) + 32*1040 + row * 1040 + j * 8) = lo;
        }
    }
    if (t < 32) { smM[t] = -1e30f; smL[t] = 0.0f; }
    __syncthreads();

    FC acc[2][2];
#pragma unroll
    for (int pt = 0; pt < 2; pt++)
#pragma unroll
        for (int ht = 0; ht < 2; ht++) wmma::fill_fragment(acc[pt][ht], 0.0f);

    const int ms = wid & 1, np = (wid >> 1) & 1, kq = (wid >> 2) & 3;

    for (int c = 0; c < nsub; c++) {
        const int cur = c & 1;
        __nv_bfloat16* Xh = reinterpret_cast<__nv_bfloat16*>(sm + OFF_X + cur * XBUF_SZ);
        __nv_bfloat16* Xl = Xh + 32 * LDX;

        // ---- issue next-chunk LDGs early (latency hides under GEMM1)
        float4 v[8];
        if (c + 1 < nsub) {
#pragma unroll
            for (int i = 0; i < 8; i++) {
                int idx = i * 512 + t;
                int row = idx >> 7, j = idx & 127;
                v[i] = *reinterpret_cast<const float4*>(
                    x + xb + ((size_t)(sub0 + c + 1) * 32 + row) * H_ + j * 4);
            }
        }

        // ---- GEMM1: warp = (ms, np, kq); 8 k-steps in 2 interleaved accs
        {
            FC s0, s1;
            wmma::fill_fragment(s0, 0.0f);
            wmma::fill_fragment(s1, 0.0f);
#pragma unroll
            for (int kk = 0; kk < 4; kk++) {
                const int ko = kq * 128 + kk * 32;
                {
                    FA ah, al; FBc bh, bl;
                    wmma::load_matrix_sync(ah, Xh + ms * 16 * LDX + ko, LDX);
                    wmma::load_matrix_sync(al, Xl + ms * 16 * LDX + ko, LDX);
                    wmma::load_matrix_sync(bh, Phi + np * 16 * LDX + ko, LDX);
                    wmma::load_matrix_sync(bl, Plo + np * 16 * LDX + ko, LDX);
                    wmma::mma_sync(s0, ah, bh, s0);
                    wmma::mma_sync(s0, ah, bl, s0);
                    wmma::mma_sync(s0, al, bh, s0);
                }
                {
                    FA ah, al; FBc bh, bl;
                    wmma::load_matrix_sync(ah, Xh + ms * 16 * LDX + ko + 16, LDX);
                    wmma::load_matrix_sync(al, Xl + ms * 16 * LDX + ko + 16, LDX);
                    wmma::load_matrix_sync(bh, Phi + np * 16 * LDX + ko + 16, LDX);
                    wmma::load_matrix_sync(bl, Plo + np * 16 * LDX + ko + 16, LDX);
                    wmma::mma_sync(s1, ah, bh, s1);
                    wmma::mma_sync(s1, ah, bl, s1);
                    wmma::mma_sync(s1, al, bh, s1);
                }
            }
#pragma unroll
            for (int i = 0; i < 8; i++) s0.x[i] += s1.x[i];
            wmma::store_matrix_sync(Sb + kq * (SBUF_SZ/4) + ms * 16 * LDS_ + np * 16,
                                    s0, LDS_, wmma::mem_row_major);
        }

        // ---- split + store next chunk into other buffer
        if (c + 1 < nsub) {
            __nv_bfloat16* Nh = reinterpret_cast<__nv_bfloat16*>(
                sm + OFF_X + (cur ^ 1) * XBUF_SZ);
#pragma unroll
            for (int i = 0; i < 8; i++) {
                int idx = i * 512 + t;
                int row = idx >> 7, j = idx & 127;
                uint2 hi, lo; split4(v[i], hi, lo);
                *reinterpret_cast<uint2*>(reinterpret_cast<char*>(Nh) + row * 1040 + j * 8) = hi;
                *reinterpret_cast<uint2*>(reinterpret_cast<char*>(Nh) + 32*1040 + row * 1040 + j * 8) = lo;
            }
        }
        __syncthreads();   // S complete, next X staged

        // ---- online-softmax stats + E tile (warp w: probes 2w, 2w+1)
#pragma unroll
        for (int c2 = 0; c2 < 2; c2++) {
            const int p = wid * 2 + c2;
            float sv = Sb[lane * LDS_ + p] + Sb[(SBUF_SZ/4) + lane * LDS_ + p]
                     + Sb[2*(SBUF_SZ/4) + lane * LDS_ + p]
                     + Sb[3*(SBUF_SZ/4) + lane * LDS_ + p];
            float cm = sv;
#pragma unroll
            for (int o = 16; o > 0; o >>= 1)
                cm = fmaxf(cm, __shfl_xor_sync(0xFFFFFFFFu, cm, o));
            const float mo = smM[p];
            const float mn = fmaxf(mo, cm);
            const float e = __expf(sv - mn);
            float se = e;
#pragma unroll
            for (int o = 16; o > 0; o >>= 1)
                se += __shfl_xor_sync(0xFFFFFFFFu, se, o);
            if (lane == 0) {
                const float sc = __expf(mo - mn);
                smSC[p] = sc;
                smM[p]  = mn;
                smL[p]  = smL[p] * sc + se;
            }
            __nv_bfloat16 eh = __float2bfloat16_rn(e);
            __nv_bfloat16 el = __float2bfloat16_rn(e - __bfloat162float(eh));
            Ehi[p * LDE + lane] = eh;
            Elo[p * LDE + lane] = el;
        }
        __syncthreads();   // E + scale visible

        // ---- rescale acc (m16n8k16 layout: x[0..1] row lane>>2, x[2..3] row+8)
#pragma unroll
        for (int pt = 0; pt < 2; pt++) {
            const float sa = smSC[pt * 16 + (lane >> 2)];
            const float sb = smSC[pt * 16 + (lane >> 2) + 8];
#pragma unroll
            for (int ht = 0; ht < 2; ht++)
#pragma unroll
                for (int i = 0; i < 8; i++)
                    acc[pt][ht].x[i] *= (i & 2) ? sb : sa;
        }

        // ---- GEMM2: warp h-slab = 32 h at wid*32
#pragma unroll
        for (int kk = 0; kk < 2; kk++) {
            FA ah[2], al[2];
#pragma unroll
            for (int pt = 0; pt < 2; pt++) {
                wmma::load_matrix_sync(ah[pt], Ehi + pt * 16 * LDE + kk * 16, LDE);
                wmma::load_matrix_sync(al[pt], Elo + pt * 16 * LDE + kk * 16, LDE);
            }
#pragma unroll
            for (int ht = 0; ht < 2; ht++) {
                FBr bh, bl;
                wmma::load_matrix_sync(bh, Xh + kk * 16 * LDX + wid * 32 + ht * 16, LDX);
                wmma::load_matrix_sync(bl, Xl + kk * 16 * LDX + wid * 32 + ht * 16, LDX);
#pragma unroll
                for (int pt = 0; pt < 2; pt++) {
                    wmma::mma_sync(acc[pt][ht], ah[pt], bh, acc[pt][ht]);
                    wmma::mma_sync(acc[pt][ht], ah[pt], bl, acc[pt][ht]);
                    wmma::mma_sync(acc[pt][ht], al[pt], bh, acc[pt][ht]);
                }
            }
        }
        __syncthreads();   // cur buffer free; smSC/E reusable
    }

    // ---- epilogue
#pragma unroll
    for (int pt = 0; pt < 2; pt++)
#pragma unroll
        for (int ht = 0; ht < 2; ht++)
            wmma::store_matrix_sync(
                g_part + (((size_t)(ss * B_ + b)) * P_ + pt * 16) * H_ + wid * 32 + ht * 16,
                acc[pt][ht], H_, wmma::mem_row_major);
    if (wid == 0) {
        g_m[(ss * B_ + b) * P_ + lane] = smM[lane];
        g_l[(ss * B_ + b) * P_ + lane] = smL[lane];
    }
}

// ===========================================================================
// Combine: out = sum_ss part*w / sum_ss l*w, w = exp(m_ss - m_glob). float4.
// ===========================================================================
__global__ __launch_bounds__(256) void k_final(float* __restrict__ out) {
    const int idx4 = blockIdx.x * 256 + threadIdx.x;    // 0..65535
    const int b   = idx4 >> 12;                         // / (P*H/4)
    const int ph4 = idx4 & 4095;
    const int p   = ph4 >> 7;                           // / (H/4)

    float mg = -1e30f;
#pragma unroll
    for (int ss = 0; ss < NSPL; ss++)
        mg = fmaxf(mg, g_m[(ss * B_ + b) * P_ + p]);
    float4 num = make_float4(0.f, 0.f, 0.f, 0.f);
    float den = 0.0f;
#pragma unroll
    for (int ss = 0; ss < NSPL; ss++) {
        const int base = (ss * B_ + b) * P_ + p;
        const float w = __expf(g_m[base] - mg);
        float4 pv = *reinterpret_cast<const float4*>(
            g_part + (size_t)(ss * B_ + b) * P_ * H_ + (size_t)ph4 * 4);
        num.x += pv.x * w; num.y += pv.y * w;
        num.z += pv.z * w; num.w += pv.w * w;
        den += g_l[base] * w;
    }
    const float r = 1.0f / den;
    float4 o = make_float4(num.x * r, num.y * r, num.z * r, num.w * r);
    *reinterpret_cast<float4*>(out + (size_t)idx4 * 4) = o;
}

// ---------------------------------------------------------------------------
extern "C" void kernel_launch(void* const* d_in, const int* in_sizes, int n_in,
                              void* d_out, int out_size) {
    const float* x     = (const float*)d_in[0];   // [B, S, H]
    const float* probe = (const float*)d_in[1];   // [P, H]
    float* out = (float*)d_out;                   // [B, P*H]

    cudaFuncSetAttribute(k_fused, cudaFuncAttributeMaxDynamicSharedMemorySize,
                         SMEM_TOT);

    k_fused<<< dim3(NSPL, B_), 512, SMEM_TOT >>>(x, probe);
    k_final<<< (B_ * P_ * H_ / 4) / 256, 256 >>>(out);
}

// round 17
// speedup vs baseline: 1.9707x; 1.2091x over previous
#include <cuda_runtime.h>
#include <cuda_bf16.h>
#include <mma.h>
#include <cstdint>

using namespace nvcuda;

#define B_ 16
#define S_ 8192
#define H_ 512
#define P_ 32
#define NSPL 9            // s-splits -> 9*16 = 144 CTAs = 1 wave

// Scratch (device globals; no allocation anywhere)
__device__ float g_part[NSPL*B_*P_*H_];   // per-split unnormalized ctx
__device__ float g_m[NSPL*B_*P_];         // per-split running max
__device__ float g_l[NSPL*B_*P_];         // per-split exp-sum

// ---------------- smem layout (bytes) ----------------
#define LDX 520                               // bf16 elems per row (512 + 8 pad)
#define LDS_ 36                               // S tile stride (floats, 144B)
#define LDE 48                                // E tile stride (bf16)
#define XROW 1040                             // LDX * 2 bytes
#define OFF_PHI   0
#define OFF_PLO   (OFF_PHI + 32*LDX*2)        // 33280
#define OFF_X     (OFF_PLO + 32*LDX*2)        // 66560
#define XBUF_SZ   (32*LDX*2*2)                // hi+lo per buffer = 66560
#define OFF_S     (OFF_X + 2*XBUF_SZ)         // 199680
#define SBUF_SZ   (32*LDS_*4)                 // 4608; layout S[buf][kq]
#define OFF_E     (OFF_S + 4*SBUF_SZ)         // 218112; E[buf]{hi,lo} 4 x 3072
#define EBUF_SZ   (32*LDE*2)                  // 3072
#define OFF_M     (OFF_E + 4*EBUF_SZ)         // 230400
#define OFF_L     (OFF_M + 128)               // 230528
#define OFF_SC    (OFF_L + 128)               // 230656; smSC[2][32]
#define SMEM_TOT  (OFF_SC + 256)              // 230912

// named barriers: SE=1+i, SF=3+i, XE=5+i, XF=7+i, Pbar=9, Cbar=10
__device__ __forceinline__ void bsync(int id, int n) {
    asm volatile("bar.sync %0, %1;" :: "r"(id), "r"(n) : "memory");
}
__device__ __forceinline__ void barrv(int id, int n) {
    asm volatile("bar.arrive %0, %1;" :: "r"(id), "r"(n) : "memory");
}

// fast fp32 -> (hi, lo) bf16 split for a float4
__device__ __forceinline__ void split4(float4 v, uint2& hi, uint2& lo) {
    uint32_t h01, h23;
    asm("cvt.rn.bf16x2.f32 %0, %1, %2;" : "=r"(h01) : "f"(v.y), "f"(v.x));
    asm("cvt.rn.bf16x2.f32 %0, %1, %2;" : "=r"(h23) : "f"(v.w), "f"(v.z));
    float hx = __uint_as_float(h01 << 16);
    float hy = __uint_as_float(h01 & 0xFFFF0000u);
    float hz = __uint_as_float(h23 << 16);
    float hw = __uint_as_float(h23 & 0xFFFF0000u);
    uint32_t l01, l23;
    asm("cvt.rn.bf16x2.f32 %0, %1, %2;" : "=r"(l01) : "f"(v.y - hy), "f"(v.x - hx));
    asm("cvt.rn.bf16x2.f32 %0, %1, %2;" : "=r"(l23) : "f"(v.w - hw), "f"(v.z - hz));
    hi = make_uint2(h01, h23);
    lo = make_uint2(l01, l23);
}

typedef wmma::fragment<wmma::matrix_a, 16, 16, 16, __nv_bfloat16, wmma::row_major> FA;
typedef wmma::fragment<wmma::matrix_b, 16, 16, 16, __nv_bfloat16, wmma::col_major> FBc;
typedef wmma::fragment<wmma::matrix_b, 16, 16, 16, __nv_bfloat16, wmma::row_major> FBr;
typedef wmma::fragment<wmma::accumulator, 16, 16, 16, float> FC;

// ===========================================================================
// Warp-specialized fused kernel. CTA = (ss, b). 512 threads.
// P-side (warps 0-7): stage X chunk (LDG+split+STS), GEMM1 S = x*P^T.
// C-side (warps 8-15): softmax stats + E, rescale, GEMM2 ctx += E*x (acc in regs).
// Named-barrier ping-pong on X[2] and S[2]; E/SC double-buffered.
// ===========================================================================
__global__ __launch_bounds__(512, 1) void k_fused(const float* __restrict__ x,
                                                  const float* __restrict__ probe) {
    extern __shared__ unsigned char sm[];
    __nv_bfloat16* Phi = reinterpret_cast<__nv_bfloat16*>(sm + OFF_PHI);
    __nv_bfloat16* Plo = reinterpret_cast<__nv_bfloat16*>(sm + OFF_PLO);
    float* smM  = reinterpret_cast<float*>(sm + OFF_M);
    float* smL  = reinterpret_cast<float*>(sm + OFF_L);

    const int t = threadIdx.x, wid = t >> 5, lane = t & 31;
    const int ss = blockIdx.x, b = blockIdx.y;
    const int nsub = (ss < 4) ? 29 : 28;               // 4*29 + 5*28 = 256
    const int sub0 = ss * 28 + (ss < 4 ? ss : 4);
    const size_t xb = (size_t)b * S_ * H_;

    // ---- prologue (all 512): probes + chunk 0 into X[0]
#pragma unroll
    for (int i = 0; i < 8; i++) {
        int idx = i * 512 + t;
        int p = idx >> 7, j = idx & 127;
        float4 v = *reinterpret_cast<const float4*>(probe + (size_t)p * H_ + j * 4);
        uint2 hi, lo; split4(v, hi, lo);
        *reinterpret_cast<uint2*>(reinterpret_cast<char*>(Phi) + p * XROW + j * 8) = hi;
        *reinterpret_cast<uint2*>(reinterpret_cast<char*>(Plo) + p * XROW + j * 8) = lo;
    }
    {
        unsigned char* X0 = sm + OFF_X;
#pragma unroll
        for (int i = 0; i < 8; i++) {
            int idx = i * 512 + t;
            int row = idx >> 7, j = idx & 127;
            float4 v = *reinterpret_cast<const float4*>(
                x + xb + ((size_t)sub0 * 32 + row) * H_ + j * 4);
            uint2 hi, lo; split4(v, hi, lo);
            *reinterpret_cast<uint2*>(X0 + row * XROW + j * 8) = hi;
            *reinterpret_cast<uint2*>(X0 + 32 * XROW + row * XROW + j * 8) = lo;
        }
    }
    if (t < 32) { smM[t] = -1e30f; smL[t] = 0.0f; }
    __syncthreads();

    if (wid < 8) {
        // =================== P-side: producer ===================
        const int ms = wid & 1, np = (wid >> 1) & 1, kq = (wid >> 2) & 1;
        for (int c = 0; c < nsub; c++) {
            const int idx = c & 1;
            __nv_bfloat16* Xh = reinterpret_cast<__nv_bfloat16*>(sm + OFF_X + idx * XBUF_SZ);
            __nv_bfloat16* Xl = Xh + 32 * LDX;

            if (c >= 2) bsync(1 + idx, 512);       // SE: stats(c-2) done with S[idx]
            // ---- GEMM1: 16 k-steps of 16, two interleaved accumulators
            FC s0, s1;
            wmma::fill_fragment(s0, 0.0f);
            wmma::fill_fragment(s1, 0.0f);
#pragma unroll
            for (int st = 0; st < 8; st++) {
                const int ko = kq * 256 + st * 32;
                {
                    FA ah, al; FBc bh, bl;
                    wmma::load_matrix_sync(ah, Xh + ms * 16 * LDX + ko, LDX);
                    wmma::load_matrix_sync(al, Xl + ms * 16 * LDX + ko, LDX);
                    wmma::load_matrix_sync(bh, Phi + np * 16 * LDX + ko, LDX);
                    wmma::load_matrix_sync(bl, Plo + np * 16 * LDX + ko, LDX);
                    wmma::mma_sync(s0, ah, bh, s0);
                    wmma::mma_sync(s0, ah, bl, s0);
                    wmma::mma_sync(s0, al, bh, s0);
                }
                {
                    FA ah, al; FBc bh, bl;
                    wmma::load_matrix_sync(ah, Xh + ms * 16 * LDX + ko + 16, LDX);
                    wmma::load_matrix_sync(al, Xl + ms * 16 * LDX + ko + 16, LDX);
                    wmma::load_matrix_sync(bh, Phi + np * 16 * LDX + ko + 16, LDX);
                    wmma::load_matrix_sync(bl, Plo + np * 16 * LDX + ko + 16, LDX);
                    wmma::mma_sync(s1, ah, bh, s1);
                    wmma::mma_sync(s1, ah, bl, s1);
                    wmma::mma_sync(s1, al, bh, s1);
                }
            }
#pragma unroll
            for (int i = 0; i < 8; i++) s0.x[i] += s1.x[i];
            wmma::store_matrix_sync(
                reinterpret_cast<float*>(sm + OFF_S + (idx * 2 + kq) * SBUF_SZ)
                    + ms * 16 * LDS_ + np * 16,
                s0, LDS_, wmma::mem_row_major);
            barrv(3 + idx, 512);                   // SF: S[idx] ready

            // ---- stage X for chunk c+1
            if (c + 1 < nsub) {
                const int i2 = (c + 1) & 1;
                if (c >= 1) bsync(5 + i2, 512);    // XE: GEMM2(c-1) done with X[i2]
                unsigned char* N = sm + OFF_X + i2 * XBUF_SZ;
#pragma unroll
                for (int i = 0; i < 16; i++) {
                    int idx2 = i * 256 + t;
                    int row = idx2 >> 7, j = idx2 & 127;
                    float4 v = *reinterpret_cast<const float4*>(
                        x + xb + ((size_t)(sub0 + c + 1) * 32 + row) * H_ + j * 4);
                    uint2 hi, lo; split4(v, hi, lo);
                    *reinterpret_cast<uint2*>(N + row * XROW + j * 8) = hi;
                    *reinterpret_cast<uint2*>(N + 32 * XROW + row * XROW + j * 8) = lo;
                }
                bsync(9, 256);                     // P-internal: X[i2] fully written
                barrv(7 + i2, 512);                // XF: X[i2] ready for GEMM2
            }
        }
    } else {
        // =================== C-side: consumer ===================
        const int cw = wid - 8;                    // 0..7, h-slab cw*64
        FC acc[2][4];
#pragma unroll
        for (int pt = 0; pt < 2; pt++)
#pragma unroll
            for (int ht = 0; ht < 4; ht++) wmma::fill_fragment(acc[pt][ht], 0.0f);

        for (int c = 0; c < nsub; c++) {
            const int idx = c & 1;
            __nv_bfloat16* Xh = reinterpret_cast<__nv_bfloat16*>(sm + OFF_X + idx * XBUF_SZ);
            __nv_bfloat16* Xl = Xh + 32 * LDX;
            float* Sq0 = reinterpret_cast<float*>(sm + OFF_S + (idx * 2 + 0) * SBUF_SZ);
            float* Sq1 = reinterpret_cast<float*>(sm + OFF_S + (idx * 2 + 1) * SBUF_SZ);
            __nv_bfloat16* Ehi = reinterpret_cast<__nv_bfloat16*>(sm + OFF_E + idx * 2 * EBUF_SZ);
            __nv_bfloat16* Elo = Ehi + 32 * LDE;
            float* smSC = reinterpret_cast<float*>(sm + OFF_SC + idx * 128);

            bsync(3 + idx, 512);                   // SF: wait S[idx]
            // ---- stats + E (warp cw: probes 4cw..4cw+3)
#pragma unroll
            for (int c4 = 0; c4 < 4; c4++) {
                const int p = cw * 4 + c4;
                float sv = Sq0[lane * LDS_ + p] + Sq1[lane * LDS_ + p];
                float cm = sv;
#pragma unroll
                for (int o = 16; o > 0; o >>= 1)
                    cm = fmaxf(cm, __shfl_xor_sync(0xFFFFFFFFu, cm, o));
                const float mo = smM[p];
                const float mn = fmaxf(mo, cm);
                const float e = __expf(sv - mn);
                float se = e;
#pragma unroll
                for (int o = 16; o > 0; o >>= 1)
                    se += __shfl_xor_sync(0xFFFFFFFFu, se, o);
                if (lane == 0) {
                    const float sc = __expf(mo - mn);
                    smSC[p] = sc;
                    smM[p]  = mn;
                    smL[p]  = smL[p] * sc + se;
                }
                __nv_bfloat16 eh = __float2bfloat16_rn(e);
                __nv_bfloat16 el = __float2bfloat16_rn(e - __bfloat162float(eh));
                Ehi[p * LDE + lane] = eh;
                Elo[p * LDE + lane] = el;
            }
            bsync(10, 256);                        // C-internal: E/SC visible
            barrv(1 + idx, 512);                   // SE: done reading S[idx]

            // ---- rescale acc (m16n8k16: x[0..1] row lane>>2, x[2..3] row+8)
#pragma unroll
            for (int pt = 0; pt < 2; pt++) {
                const float sa = smSC[pt * 16 + (lane >> 2)];
                const float sb = smSC[pt * 16 + (lane >> 2) + 8];
#pragma unroll
                for (int ht = 0; ht < 4; ht++)
#pragma unroll
                    for (int i = 0; i < 8; i++)
                        acc[pt][ht].x[i] *= (i & 2) ? sb : sa;
            }

            if (c >= 1) bsync(7 + idx, 512);       // XF: wait X[idx] (c=0: prologue)
            // ---- GEMM2: ctx[32p, 64h @ cw*64] += E * X
#pragma unroll
            for (int kk = 0; kk < 2; kk++) {
#pragma unroll
                for (int pt = 0; pt < 2; pt++) {
                    FA ah, al;
                    wmma::load_matrix_sync(ah, Ehi + pt * 16 * LDE + kk * 16, LDE);
                    wmma::load_matrix_sync(al, Elo + pt * 16 * LDE + kk * 16, LDE);
#pragma unroll
                    for (int ht = 0; ht < 4; ht++) {
                        FBr bh, bl;
                        wmma::load_matrix_sync(bh, Xh + kk * 16 * LDX + cw * 64 + ht * 16, LDX);
                        wmma::load_matrix_sync(bl, Xl + kk * 16 * LDX + cw * 64 + ht * 16, LDX);
                        wmma::mma_sync(acc[pt][ht], ah, bh, acc[pt][ht]);
                        wmma::mma_sync(acc[pt][ht], ah, bl, acc[pt][ht]);
                        wmma::mma_sync(acc[pt][ht], al, bh, acc[pt][ht]);
                    }
                }
            }
            barrv(5 + idx, 512);                   // XE: done reading X[idx]
        }

        // ---- epilogue
#pragma unroll
        for (int pt = 0; pt < 2; pt++)
#pragma unroll
            for (int ht = 0; ht < 4; ht++)
                wmma::store_matrix_sync(
                    g_part + (((size_t)(ss * B_ + b)) * P_ + pt * 16) * H_ + cw * 64 + ht * 16,
                    acc[pt][ht], H_, wmma::mem_row_major);
        if (cw == 0) {
            g_m[(ss * B_ + b) * P_ + lane] = smM[lane];
            g_l[(ss * B_ + b) * P_ + lane] = smL[lane];
        }
    }
}

// ===========================================================================
// Combine: out = sum_ss part*w / sum_ss l*w, w = exp(m_ss - m_glob). float4.
// ===========================================================================
__global__ __launch_bounds__(256) void k_final(float* __restrict__ out) {
    const int idx4 = blockIdx.x * 256 + threadIdx.x;    // 0..65535
    const int b   = idx4 >> 12;
    const int ph4 = idx4 & 4095;
    const int p   = ph4 >> 7;

    float mg = -1e30f;
#pragma unroll
    for (int ss = 0; ss < NSPL; ss++)
        mg = fmaxf(mg, g_m[(ss * B_ + b) * P_ + p]);
    float4 num = make_float4(0.f, 0.f, 0.f, 0.f);
    float den = 0.0f;
#pragma unroll
    for (int ss = 0; ss < NSPL; ss++) {
        const int base = (ss * B_ + b) * P_ + p;
        const float w = __expf(g_m[base] - mg);
        float4 pv = *reinterpret_cast<const float4*>(
            g_part + (size_t)(ss * B_ + b) * P_ * H_ + (size_t)ph4 * 4);
        num.x += pv.x * w; num.y += pv.y * w;
        num.z += pv.z * w; num.w += pv.w * w;
        den += g_l[base] * w;
    }
    const float r = 1.0f / den;
    float4 o = make_float4(num.x * r, num.y * r, num.z * r, num.w * r);
    *reinterpret_cast<float4*>(out + (size_t)idx4 * 4) = o;
}

// ---------------------------------------------------------------------------
extern "C" void kernel_launch(void* const* d_in, const int* in_sizes, int n_in,
                              void* d_out, int out_size) {
    const float* x     = (const float*)d_in[0];   // [B, S, H]
    const float* probe = (const float*)d_in[1];   // [P, H]
    float* out = (float*)d_out;                   // [B, P*H]

    cudaFuncSetAttribute(k_fused, cudaFuncAttributeMaxDynamicSharedMemorySize,
                         SMEM_TOT);

    k_fused<<< dim3(NSPL, B_), 512, SMEM_TOT >>>(x, probe);
    k_final<<< (B_ * P_ * H_ / 4) / 256, 256 >>>(out);
}